// round 1
// baseline (speedup 1.0000x reference)
#include <cuda_runtime.h>
#include <math.h>

// Problem constants
#define B_ 2
#define S_ 1024
#define D_ 1024
#define H_ 16
#define DH_ 64
#define L_ 8
#define FF_ 4096
#define V_ 32000
#define BS_ (B_ * S_)

// ---------------- scratch (device globals: allocation-guard safe) ----------
__device__ float g_h[BS_ * D_];
__device__ float g_xn[BS_ * D_];
__device__ float g_q[BS_ * D_];
__device__ float g_k[BS_ * D_];
__device__ float g_v[BS_ * D_];
__device__ float g_o[BS_ * D_];
__device__ float g_ff[BS_ * FF_];
__device__ float g_wq[L_ * D_ * D_];
__device__ float g_wk[L_ * D_ * D_];
__device__ float g_wv[L_ * D_ * D_];

// ---------------- reductions ----------------
__device__ __forceinline__ float warpReduceSum(float v) {
    #pragma unroll
    for (int o = 16; o > 0; o >>= 1) v += __shfl_xor_sync(0xffffffffu, v, o);
    return v;
}
__device__ __forceinline__ float warpReduceMax(float v) {
    #pragma unroll
    for (int o = 16; o > 0; o >>= 1) v = fmaxf(v, __shfl_xor_sync(0xffffffffu, v, o));
    return v;
}

// Block reduce returning result to ALL threads. Leading sync makes it safe
// to call repeatedly with the same static shared buffer.
__device__ float blockReduceSum(float v) {
    __shared__ float sh[33];
    __syncthreads();
    int lane = threadIdx.x & 31, w = threadIdx.x >> 5;
    v = warpReduceSum(v);
    if (lane == 0) sh[w] = v;
    __syncthreads();
    int nw = (blockDim.x + 31) >> 5;
    float r = (threadIdx.x < nw) ? sh[threadIdx.x] : 0.0f;
    if (w == 0) {
        r = warpReduceSum(r);
        if (lane == 0) sh[32] = r;
    }
    __syncthreads();
    return sh[32];
}
__device__ float blockReduceMax(float v) {
    __shared__ float sh[33];
    __syncthreads();
    int lane = threadIdx.x & 31, w = threadIdx.x >> 5;
    v = warpReduceMax(v);
    if (lane == 0) sh[w] = v;
    __syncthreads();
    int nw = (blockDim.x + 31) >> 5;
    float r = (threadIdx.x < nw) ? sh[threadIdx.x] : -3.0e38f;
    if (w == 0) {
        r = warpReduceMax(r);
        if (lane == 0) sh[32] = r;
    }
    __syncthreads();
    return sh[32];
}

// ---------------- repack [L,H,D,DH] -> [L,D,H*DH] ----------------
__global__ void repack_kernel(const float* __restrict__ W, float* __restrict__ Wt, int total) {
    int i = blockIdx.x * blockDim.x + threadIdx.x;
    if (i >= total) return;
    int e = i % DH_;
    int t = i / DH_;
    int d = t % D_;
    t /= D_;
    int h = t % H_;
    int l = t / H_;
    Wt[((size_t)(l * D_ + d)) * D_ + h * DH_ + e] = W[i];
}

// ---------------- embedding ----------------
__global__ void embed_kernel(const int* __restrict__ tokens,
                             const float* __restrict__ tok_emb,
                             const float* __restrict__ pos_emb,
                             float* __restrict__ h) {
    int i = blockIdx.x * blockDim.x + threadIdx.x;
    if (i >= BS_ * D_) return;
    int d = i % D_;
    int bs = i / D_;
    int s = bs % S_;
    int tok = tokens[bs];
    h[i] = tok_emb[(size_t)tok * D_ + d] + pos_emb[(size_t)s * D_ + d];
}

// ---------------- layernorm: one block per row, 256 threads, D=1024 --------
__global__ void layernorm_kernel(const float* __restrict__ x,
                                 const float* __restrict__ g,
                                 const float* __restrict__ b,
                                 float* __restrict__ y) {
    int row = blockIdx.x;
    const float* xr = x + (size_t)row * D_;
    float* yr = y + (size_t)row * D_;
    float vals[4];
    float s = 0.0f;
    #pragma unroll
    for (int j = 0; j < 4; j++) {
        vals[j] = xr[threadIdx.x + j * 256];
        s += vals[j];
    }
    float mean = blockReduceSum(s) * (1.0f / D_);
    float var = 0.0f;
    #pragma unroll
    for (int j = 0; j < 4; j++) {
        float d = vals[j] - mean;
        var += d * d;
    }
    var = blockReduceSum(var) * (1.0f / D_);
    float rstd = rsqrtf(var + 1e-5f);
    #pragma unroll
    for (int j = 0; j < 4; j++) {
        int i = threadIdx.x + j * 256;
        yr[i] = (vals[j] - mean) * rstd * g[i] + b[i];
    }
}

// ---------------- tiled SGEMM: C = A[MxK] * B[KxN] (+bias)(+resid)(relu) ---
#define BM 64
#define BN 64
#define BK 16
template <bool BIAS, bool RESID, bool RELU>
__global__ __launch_bounds__(256) void sgemm_kernel(
    const float* __restrict__ A, const float* __restrict__ Bm,
    const float* __restrict__ bias, const float* __restrict__ resid,
    float* __restrict__ C, int M, int N, int K) {
    __shared__ float As[BK][BM + 4];
    __shared__ float Bs[BK][BN + 4];
    int tid = threadIdx.x;
    int tx = tid & 15, ty = tid >> 4;
    int row0 = blockIdx.y * BM;
    int col0 = blockIdx.x * BN;
    float acc[4][4] = {};
    for (int k0 = 0; k0 < K; k0 += BK) {
        #pragma unroll
        for (int i = tid; i < BM * BK; i += 256) {
            int r = i >> 4, c = i & 15;
            As[c][r] = A[(size_t)(row0 + r) * K + k0 + c];
        }
        #pragma unroll
        for (int i = tid; i < BK * BN; i += 256) {
            int r = i >> 6, c = i & 63;
            Bs[r][c] = Bm[(size_t)(k0 + r) * N + col0 + c];
        }
        __syncthreads();
        #pragma unroll
        for (int kk = 0; kk < BK; kk++) {
            float a[4], bb[4];
            #pragma unroll
            for (int i = 0; i < 4; i++) a[i] = As[kk][ty * 4 + i];
            #pragma unroll
            for (int j = 0; j < 4; j++) bb[j] = Bs[kk][tx * 4 + j];
            #pragma unroll
            for (int i = 0; i < 4; i++)
                #pragma unroll
                for (int j = 0; j < 4; j++) acc[i][j] = fmaf(a[i], bb[j], acc[i][j]);
        }
        __syncthreads();
    }
    #pragma unroll
    for (int i = 0; i < 4; i++) {
        int r = row0 + ty * 4 + i;
        if (r >= M) continue;
        #pragma unroll
        for (int j = 0; j < 4; j++) {
            int c = col0 + tx * 4 + j;
            if (c >= N) continue;
            float vv = acc[i][j];
            if (BIAS) vv += bias[c];
            if (RESID) vv += resid[(size_t)r * N + c];
            if (RELU) vv = fmaxf(vv, 0.0f);
            C[(size_t)r * N + c] = vv;
        }
    }
}

static void run_sgemm(const float* A, const float* Bm, const float* bias,
                      const float* resid, float* C, int M, int N, int K,
                      bool hasBias, bool hasResid, bool relu) {
    dim3 grid((N + BN - 1) / BN, (M + BM - 1) / BM);
    if (hasBias && hasResid)
        sgemm_kernel<true, true, false><<<grid, 256>>>(A, Bm, bias, resid, C, M, N, K);
    else if (hasBias && relu)
        sgemm_kernel<true, false, true><<<grid, 256>>>(A, Bm, bias, resid, C, M, N, K);
    else if (hasBias)
        sgemm_kernel<true, false, false><<<grid, 256>>>(A, Bm, bias, resid, C, M, N, K);
    else
        sgemm_kernel<false, false, false><<<grid, 256>>>(A, Bm, bias, resid, C, M, N, K);
}

// ---------------- fused causal attention: one block per (q, h, b) ----------
// Q/K/V/O layout: [b, s, h*DH + e] (row stride D)
__global__ __launch_bounds__(128) void attention_kernel(
    const float* __restrict__ Q, const float* __restrict__ K,
    const float* __restrict__ V, float* __restrict__ O) {
    int q = blockIdx.x, h = blockIdx.y, b = blockIdx.z;
    const float scale = 0.03125f;  // D^-0.5 = 1024^-0.5 (reference scales by D, not DH)
    __shared__ float sQ[DH_];
    __shared__ float sS[S_];
    __shared__ float sAcc[128];
    int tid = threadIdx.x;
    size_t qbase = ((size_t)(b * S_ + q)) * D_ + h * DH_;
    if (tid < DH_) sQ[tid] = Q[qbase + tid];
    __syncthreads();

    int nk = q + 1;
    float lmax = -3.0e38f;
    for (int k = tid; k < nk; k += 128) {
        const float* kr = K + ((size_t)(b * S_ + k)) * D_ + h * DH_;
        float s = 0.0f;
        #pragma unroll
        for (int e = 0; e < DH_; e++) s = fmaf(sQ[e], kr[e], s);
        s *= scale;
        sS[k] = s;
        lmax = fmaxf(lmax, s);
    }
    float m = blockReduceMax(lmax);
    float lsum = 0.0f;
    for (int k = tid; k < nk; k += 128) {  // each thread revisits only its own sS entries
        float p = expf(sS[k] - m);
        sS[k] = p;
        lsum += p;
    }
    float denom = blockReduceSum(lsum);  // internal syncs publish sS to all threads
    float inv = 1.0f / denom;

    int e = tid & 63, half = tid >> 6;
    float acc = 0.0f;
    for (int k = half; k < nk; k += 2)
        acc = fmaf(sS[k], V[((size_t)(b * S_ + k)) * D_ + h * DH_ + e], acc);
    sAcc[tid] = acc;
    __syncthreads();
    if (tid < DH_) O[qbase + tid] = (sAcc[tid] + sAcc[tid + 64]) * inv;
}

// ---------------- loss ----------------
__global__ void zero_kernel(float* p) { *p = 0.0f; }

__global__ void loss_kernel(const float* __restrict__ logits,
                            const int* __restrict__ targets,
                            float* __restrict__ loss, float invN) {
    int row = blockIdx.x;
    const float* lr = logits + (size_t)row * V_;
    float lmax = -3.0e38f;
    for (int i = threadIdx.x; i < V_; i += blockDim.x) lmax = fmaxf(lmax, lr[i]);
    float m = blockReduceMax(lmax);
    float lsum = 0.0f;
    for (int i = threadIdx.x; i < V_; i += blockDim.x) lsum += expf(lr[i] - m);
    float s = blockReduceSum(lsum);
    if (threadIdx.x == 0) {
        float lse = m + logf(s);
        float nll = lse - lr[targets[row]];
        atomicAdd(loss, nll * invN);
    }
}

// ---------------- launch ----------------
extern "C" void kernel_launch(void* const* d_in, const int* in_sizes, int n_in,
                              void* d_out, int out_size) {
    const int* tokens = (const int*)d_in[0];
    const int* targets = (const int*)d_in[1];
    const float* tok_emb = (const float*)d_in[2];
    const float* pos_emb = (const float*)d_in[3];
    const float* Wq = (const float*)d_in[4];
    const float* Wk = (const float*)d_in[5];
    const float* Wv = (const float*)d_in[6];
    const float* Wo = (const float*)d_in[7];
    const float* bo = (const float*)d_in[8];
    const float* ln1_g = (const float*)d_in[9];
    const float* ln1_b = (const float*)d_in[10];
    const float* ln2_g = (const float*)d_in[11];
    const float* ln2_b = (const float*)d_in[12];
    const float* W1 = (const float*)d_in[13];
    const float* b1 = (const float*)d_in[14];
    const float* W2 = (const float*)d_in[15];
    const float* b2 = (const float*)d_in[16];
    const float* lnf_g = (const float*)d_in[17];
    const float* lnf_b = (const float*)d_in[18];
    const float* Wout = (const float*)d_in[19];
    const float* bout = (const float*)d_in[20];
    float* out = (float*)d_out;

    float *h, *xn, *q, *k, *v, *o, *ff, *wq, *wk, *wv;
    cudaGetSymbolAddress((void**)&h, g_h);
    cudaGetSymbolAddress((void**)&xn, g_xn);
    cudaGetSymbolAddress((void**)&q, g_q);
    cudaGetSymbolAddress((void**)&k, g_k);
    cudaGetSymbolAddress((void**)&v, g_v);
    cudaGetSymbolAddress((void**)&o, g_o);
    cudaGetSymbolAddress((void**)&ff, g_ff);
    cudaGetSymbolAddress((void**)&wq, g_wq);
    cudaGetSymbolAddress((void**)&wk, g_wk);
    cudaGetSymbolAddress((void**)&wv, g_wv);

    // Repack QKV weights to [L, D, H*DH]
    {
        int total = L_ * H_ * D_ * DH_;
        int grid = (total + 255) / 256;
        repack_kernel<<<grid, 256>>>(Wq, wq, total);
        repack_kernel<<<grid, 256>>>(Wk, wk, total);
        repack_kernel<<<grid, 256>>>(Wv, wv, total);
    }

    embed_kernel<<<(BS_ * D_ + 255) / 256, 256>>>(tokens, tok_emb, pos_emb, h);

    for (int l = 0; l < L_; l++) {
        layernorm_kernel<<<BS_, 256>>>(h, ln1_g + (size_t)l * D_, ln1_b + (size_t)l * D_, xn);
        run_sgemm(xn, wq + (size_t)l * D_ * D_, nullptr, nullptr, q, BS_, D_, D_, false, false, false);
        run_sgemm(xn, wk + (size_t)l * D_ * D_, nullptr, nullptr, k, BS_, D_, D_, false, false, false);
        run_sgemm(xn, wv + (size_t)l * D_ * D_, nullptr, nullptr, v, BS_, D_, D_, false, false, false);
        dim3 ag(S_, H_, B_);
        attention_kernel<<<ag, 128>>>(q, k, v, o);
        run_sgemm(o, Wo + (size_t)l * D_ * D_, bo + (size_t)l * D_, h, h, BS_, D_, D_, true, true, false);
        layernorm_kernel<<<BS_, 256>>>(h, ln2_g + (size_t)l * D_, ln2_b + (size_t)l * D_, xn);
        run_sgemm(xn, W1 + (size_t)l * D_ * FF_, b1 + (size_t)l * FF_, nullptr, ff, BS_, FF_, D_, true, false, true);
        run_sgemm(ff, W2 + (size_t)l * FF_ * D_, b2 + (size_t)l * D_, h, h, BS_, D_, FF_, true, true, false);
    }

    layernorm_kernel<<<BS_, 256>>>(h, lnf_g, lnf_b, xn);
    run_sgemm(xn, Wout, bout, nullptr, out, BS_, V_, D_, true, false, false);

    long long BSV = (long long)BS_ * V_;
    if ((long long)out_size > BSV) {
        zero_kernel<<<1, 1>>>(out + BSV);
        loss_kernel<<<BS_, 256>>>(out, targets, out + BSV, 1.0f / BS_);
    }
}

// round 3
// speedup vs baseline: 1.2994x; 1.2994x over previous
#include <cuda_runtime.h>
#include <cuda_bf16.h>
#include <cstdint>
#include <math.h>

// Problem constants
#define B_ 2
#define S_ 1024
#define D_ 1024
#define H_ 16
#define DH_ 64
#define L_ 8
#define FF_ 4096
#define V_ 32000
#define BS_ (B_ * S_)
#define K3D (3 * D_)    // 3072
#define K3F (3 * FF_)   // 12288

// ---------------- scratch (device globals) ----------------
__device__ float g_h[BS_ * D_];
__device__ float g_xn[BS_ * D_];
__device__ float g_qkv[BS_ * K3D];
__device__ float g_o[BS_ * D_];
__device__ float g_ff[BS_ * FF_];
__device__ __nv_bfloat16 g_abig[BS_ * K3F];
__device__ __nv_bfloat16 g_bqkv[(size_t)L_ * K3D * K3D];
__device__ __nv_bfloat16 g_bwo[(size_t)L_ * D_ * K3D];
__device__ __nv_bfloat16 g_bw1[(size_t)L_ * FF_ * K3D];
__device__ __nv_bfloat16 g_bw2[(size_t)L_ * D_ * K3F];
__device__ __nv_bfloat16 g_bwout[(size_t)V_ * K3D];

// ---------------- helpers ----------------
__device__ __forceinline__ uint32_t smem_u32(const void* p) {
    uint32_t a;
    asm("{ .reg .u64 t; cvta.to.shared.u64 t, %1; cvt.u32.u64 %0, t; }" : "=r"(a) : "l"(p));
    return a;
}
__device__ __forceinline__ void cp_async16(uint32_t dst, const void* src) {
    asm volatile("cp.async.cg.shared.global [%0], [%1], 16;" :: "r"(dst), "l"(src) : "memory");
}
__device__ __forceinline__ void cp_commit() {
    asm volatile("cp.async.commit_group;" ::: "memory");
}
template <int N>
__device__ __forceinline__ void cp_wait() {
    asm volatile("cp.async.wait_group %0;" :: "n"(N) : "memory");
}
__device__ __forceinline__ void ldmatrix_x4(uint32_t* r, uint32_t addr) {
    asm volatile("ldmatrix.sync.aligned.m8n8.x4.shared.b16 {%0,%1,%2,%3}, [%4];"
                 : "=r"(r[0]), "=r"(r[1]), "=r"(r[2]), "=r"(r[3]) : "r"(addr));
}
__device__ __forceinline__ void mma16816(float* c, const uint32_t* a, uint32_t b0, uint32_t b1) {
    asm volatile(
        "mma.sync.aligned.m16n8k16.row.col.f32.bf16.bf16.f32 "
        "{%0,%1,%2,%3}, {%4,%5,%6,%7}, {%8,%9}, {%0,%1,%2,%3};"
        : "+f"(c[0]), "+f"(c[1]), "+f"(c[2]), "+f"(c[3])
        : "r"(a[0]), "r"(a[1]), "r"(a[2]), "r"(a[3]), "r"(b0), "r"(b1));
}

// ---------------- reductions ----------------
__device__ __forceinline__ float warpReduceSum(float v) {
    #pragma unroll
    for (int o = 16; o > 0; o >>= 1) v += __shfl_xor_sync(0xffffffffu, v, o);
    return v;
}
__device__ __forceinline__ float warpReduceMax(float v) {
    #pragma unroll
    for (int o = 16; o > 0; o >>= 1) v = fmaxf(v, __shfl_xor_sync(0xffffffffu, v, o));
    return v;
}
__device__ float blockReduceSum(float v) {
    __shared__ float sh[33];
    __syncthreads();
    int lane = threadIdx.x & 31, w = threadIdx.x >> 5;
    v = warpReduceSum(v);
    if (lane == 0) sh[w] = v;
    __syncthreads();
    int nw = (blockDim.x + 31) >> 5;
    float r = (threadIdx.x < nw) ? sh[threadIdx.x] : 0.0f;
    if (w == 0) { r = warpReduceSum(r); if (lane == 0) sh[32] = r; }
    __syncthreads();
    return sh[32];
}
__device__ float blockReduceMax(float v) {
    __shared__ float sh[33];
    __syncthreads();
    int lane = threadIdx.x & 31, w = threadIdx.x >> 5;
    v = warpReduceMax(v);
    if (lane == 0) sh[w] = v;
    __syncthreads();
    int nw = (blockDim.x + 31) >> 5;
    float r = (threadIdx.x < nw) ? sh[threadIdx.x] : -3.0e38f;
    if (w == 0) { r = warpReduceMax(r); if (lane == 0) sh[32] = r; }
    __syncthreads();
    return sh[32];
}

// ---------------- weight transpose + bf16x3 split -----------------
// In:  W (per z-slice a [K,N] row-major fp32 matrix)
// Out: rows n (transposed), K' = 3K layout [hi | lo | hi]
__global__ void transpose_split_kernel(const float* __restrict__ W, __nv_bfloat16* __restrict__ out,
                                       int K, int N, long in_z_stride, long out_l_stride,
                                       int h_group, int row_off, int Kp) {
    int z = blockIdx.z;
    int l = z / h_group, h = z % h_group;
    const float* Win = W + (long)z * in_z_stride;
    __nv_bfloat16* O = out + (long)l * out_l_stride;
    int base_row = row_off + h * N;
    __shared__ float t[32][33];
    int kb = blockIdx.y * 32, nb = blockIdx.x * 32;
    #pragma unroll
    for (int j = 0; j < 4; j++) {
        int r = threadIdx.y + j * 8;
        int k = kb + r, n = nb + threadIdx.x;
        t[r][threadIdx.x] = (k < K && n < N) ? Win[(long)k * N + n] : 0.0f;
    }
    __syncthreads();
    #pragma unroll
    for (int j = 0; j < 4; j++) {
        int r = threadIdx.y + j * 8;
        int n = nb + r, k = kb + threadIdx.x;
        if (n < N && k < K) {
            float w = t[threadIdx.x][r];
            __nv_bfloat16 hi = __float2bfloat16(w);
            __nv_bfloat16 lo = __float2bfloat16(w - __bfloat162float(hi));
            long ro = (long)(base_row + n) * Kp;
            O[ro + k] = hi;
            O[ro + K + k] = lo;
            O[ro + 2 * K + k] = hi;
        }
    }
}

// Activation split: A[M,K] fp32 -> [hi | hi | lo] bf16 [M, 3K]
__global__ void act_split_kernel(const float* __restrict__ A, __nv_bfloat16* __restrict__ out, int K) {
    long i = (long)blockIdx.x * 256 + threadIdx.x;
    int k = (int)(i % K);
    long m = i / K;
    float w = A[i];
    __nv_bfloat16 hi = __float2bfloat16(w);
    __nv_bfloat16 lo = __float2bfloat16(w - __bfloat162float(hi));
    long ro = m * (long)(3 * K);
    out[ro + k] = hi;
    out[ro + K + k] = hi;
    out[ro + 2 * K + k] = lo;
}

// ---------------- mma.sync GEMM: C[M,N] = A[M,K'] * B[N,K']^T ----------------
// A: [M,K'] bf16 row-major. B: [N,K'] bf16 row-major. 128x128 CTA tile, BK=64.
// 8 warps: 4 (M) x 2 (N); warp tile 32x64. MODE: 0 none,1 bias,2 bias+resid,3 bias+relu
#define TCG_SMEM 65536
template <int MODE>
__global__ __launch_bounds__(256) void mma_gemm_kernel(
    const __nv_bfloat16* __restrict__ A, const __nv_bfloat16* __restrict__ Bw,
    const float* __restrict__ bias, const float* __restrict__ resid,
    float* __restrict__ C, int N, int K3) {
    extern __shared__ char sm[];
    uint32_t smb = smem_u32(sm);
    // layout: [0,16K) A0  [16K,32K) B0  [32K,48K) A1  [48K,64K) B1
    uint32_t bufA[2] = { smb, smb + 32768 };
    uint32_t bufB[2] = { smb + 16384, smb + 49152 };

    int tid = threadIdx.x, lane = tid & 31, wid = tid >> 5;
    int wm = wid & 3;    // m offset 32*wm
    int wn = wid >> 2;   // n offset 64*wn
    int row0 = blockIdx.y * 128, col0 = blockIdx.x * 128;

    const char* Ab = (const char*)A;
    const char* Bb = (const char*)Bw;
    long strideB = (long)K3 * 2;  // bytes per row

    // per-thread load slots: i = tid + j*256, r = i>>3 (row), cb = (i&7)*16
    int nc = K3 >> 6;

    auto load_chunk = [&](int c, int b) {
        long kcb = (long)c * 128;
        #pragma unroll
        for (int j = 0; j < 4; j++) {
            int i = tid + j * 256;
            int r = i >> 3;
            uint32_t cb = (uint32_t)(i & 7) * 16;
            uint32_t off = (uint32_t)r * 128 + cb;
            uint32_t sw = off ^ ((off >> 3) & 0x70);
            cp_async16(bufA[b] + sw, Ab + (long)(row0 + r) * strideB + kcb + cb);
            cp_async16(bufB[b] + sw, Bb + (long)(col0 + r) * strideB + kcb + cb);
        }
        cp_commit();
    };

    float acc[2][8][4];
    #pragma unroll
    for (int i = 0; i < 2; i++)
        #pragma unroll
        for (int j = 0; j < 8; j++)
            #pragma unroll
            for (int k = 0; k < 4; k++) acc[i][j][k] = 0.0f;

    load_chunk(0, 0);
    for (int c = 0; c < nc; c++) {
        int b = c & 1;
        if (c + 1 < nc) { load_chunk(c + 1, b ^ 1); cp_wait<1>(); }
        else cp_wait<0>();
        __syncthreads();

        #pragma unroll
        for (int s = 0; s < 4; s++) {
            int kb = s * 32 + (lane >> 4) * 16;
            uint32_t aF[2][4], bF[4][4];
            #pragma unroll
            for (int fm = 0; fm < 2; fm++) {
                uint32_t off = (uint32_t)(wm * 32 + fm * 16 + (lane & 15)) * 128 + kb;
                ldmatrix_x4(aF[fm], bufA[b] + (off ^ ((off >> 3) & 0x70)));
            }
            #pragma unroll
            for (int fb = 0; fb < 4; fb++) {
                uint32_t off = (uint32_t)(wn * 64 + fb * 16 + (lane & 15)) * 128 + kb;
                ldmatrix_x4(bF[fb], bufB[b] + (off ^ ((off >> 3) & 0x70)));
            }
            #pragma unroll
            for (int fm = 0; fm < 2; fm++)
                #pragma unroll
                for (int fn = 0; fn < 8; fn++) {
                    int fb = fn >> 1, odd = fn & 1;
                    mma16816(acc[fm][fn], aF[fm], bF[fb][odd], bF[fb][odd + 2]);
                }
        }
        __syncthreads();
    }

    // epilogue: direct register -> global with fused ops
    #pragma unroll
    for (int fm = 0; fm < 2; fm++) {
        #pragma unroll
        for (int fn = 0; fn < 8; fn++) {
            int gr = row0 + wm * 32 + fm * 16 + (lane >> 2);
            int gc = col0 + wn * 64 + fn * 8 + 2 * (lane & 3);
            float v0 = acc[fm][fn][0], v1 = acc[fm][fn][1];
            float v2 = acc[fm][fn][2], v3 = acc[fm][fn][3];
            if (MODE >= 1) {
                float b0 = bias[gc], b1 = bias[gc + 1];
                v0 += b0; v1 += b1; v2 += b0; v3 += b1;
            }
            if (MODE == 2) {
                v0 += resid[(long)gr * N + gc];
                v1 += resid[(long)gr * N + gc + 1];
                v2 += resid[(long)(gr + 8) * N + gc];
                v3 += resid[(long)(gr + 8) * N + gc + 1];
            }
            if (MODE == 3) {
                v0 = fmaxf(v0, 0.0f); v1 = fmaxf(v1, 0.0f);
                v2 = fmaxf(v2, 0.0f); v3 = fmaxf(v3, 0.0f);
            }
            *(float2*)&C[(long)gr * N + gc] = make_float2(v0, v1);
            *(float2*)&C[(long)(gr + 8) * N + gc] = make_float2(v2, v3);
        }
    }
}

static void run_tc(const __nv_bfloat16* A, const __nv_bfloat16* B, const float* bias,
                   const float* resid, float* C, int N, int K3, int mode) {
    dim3 grid(N / 128, BS_ / 128);
    if (mode == 0) mma_gemm_kernel<0><<<grid, 256, TCG_SMEM>>>(A, B, bias, resid, C, N, K3);
    else if (mode == 1) mma_gemm_kernel<1><<<grid, 256, TCG_SMEM>>>(A, B, bias, resid, C, N, K3);
    else if (mode == 2) mma_gemm_kernel<2><<<grid, 256, TCG_SMEM>>>(A, B, bias, resid, C, N, K3);
    else mma_gemm_kernel<3><<<grid, 256, TCG_SMEM>>>(A, B, bias, resid, C, N, K3);
}

// ---------------- embedding ----------------
__global__ void embed_kernel(const int* __restrict__ tokens,
                             const float* __restrict__ tok_emb,
                             const float* __restrict__ pos_emb,
                             float* __restrict__ h) {
    int i = blockIdx.x * blockDim.x + threadIdx.x;
    if (i >= BS_ * D_) return;
    int d = i % D_;
    int bs = i / D_;
    int s = bs % S_;
    int tok = tokens[bs];
    h[i] = tok_emb[(size_t)tok * D_ + d] + pos_emb[(size_t)s * D_ + d];
}

// ---------------- layernorm ----------------
__global__ void layernorm_kernel(const float* __restrict__ x,
                                 const float* __restrict__ g,
                                 const float* __restrict__ b,
                                 float* __restrict__ y) {
    int row = blockIdx.x;
    const float* xr = x + (size_t)row * D_;
    float* yr = y + (size_t)row * D_;
    float vals[4];
    float s = 0.0f;
    #pragma unroll
    for (int j = 0; j < 4; j++) { vals[j] = xr[threadIdx.x + j * 256]; s += vals[j]; }
    float mean = blockReduceSum(s) * (1.0f / D_);
    float var = 0.0f;
    #pragma unroll
    for (int j = 0; j < 4; j++) { float d = vals[j] - mean; var += d * d; }
    var = blockReduceSum(var) * (1.0f / D_);
    float rstd = rsqrtf(var + 1e-5f);
    #pragma unroll
    for (int j = 0; j < 4; j++) {
        int i = threadIdx.x + j * 256;
        yr[i] = (vals[j] - mean) * rstd * g[i] + b[i];
    }
}

// ---------------- fused causal attention (QKV packed [bs][3072]) -----------
__global__ __launch_bounds__(128) void attention_kernel(const float* __restrict__ QKV,
                                                        float* __restrict__ O) {
    int q = blockIdx.x, h = blockIdx.y, b = blockIdx.z;
    const float scale = 0.03125f;  // D^-0.5 (reference scales by embedding dim)
    __shared__ float sQ[DH_];
    __shared__ float sS[S_];
    __shared__ float sAcc[128];
    int tid = threadIdx.x;
    size_t qrow = ((size_t)(b * S_ + q)) * K3D + h * DH_;
    if (tid < DH_) sQ[tid] = QKV[qrow + tid];
    __syncthreads();

    int nk = q + 1;
    float lmax = -3.0e38f;
    for (int k = tid; k < nk; k += 128) {
        const float* kr = QKV + ((size_t)(b * S_ + k)) * K3D + D_ + h * DH_;
        float s = 0.0f;
        #pragma unroll
        for (int e = 0; e < DH_; e++) s = fmaf(sQ[e], kr[e], s);
        s *= scale;
        sS[k] = s;
        lmax = fmaxf(lmax, s);
    }
    float m = blockReduceMax(lmax);
    float lsum = 0.0f;
    for (int k = tid; k < nk; k += 128) {
        float p = expf(sS[k] - m);
        sS[k] = p;
        lsum += p;
    }
    float denom = blockReduceSum(lsum);
    float inv = 1.0f / denom;

    int e = tid & 63, half = tid >> 6;
    float acc = 0.0f;
    for (int k = half; k < nk; k += 2)
        acc = fmaf(sS[k], QKV[((size_t)(b * S_ + k)) * K3D + 2 * D_ + h * DH_ + e], acc);
    sAcc[tid] = acc;
    __syncthreads();
    if (tid < DH_) O[((size_t)(b * S_ + q)) * D_ + h * DH_ + tid] = (sAcc[tid] + sAcc[tid + 64]) * inv;
}

// ---------------- loss ----------------
__global__ void zero_kernel(float* p) { *p = 0.0f; }

__global__ void loss_kernel(const float* __restrict__ logits,
                            const int* __restrict__ targets,
                            float* __restrict__ loss, float invN) {
    int row = blockIdx.x;
    const float* lr = logits + (size_t)row * V_;
    float lmax = -3.0e38f;
    for (int i = threadIdx.x; i < V_; i += blockDim.x) lmax = fmaxf(lmax, lr[i]);
    float m = blockReduceMax(lmax);
    float lsum = 0.0f;
    for (int i = threadIdx.x; i < V_; i += blockDim.x) lsum += expf(lr[i] - m);
    float s = blockReduceSum(lsum);
    if (threadIdx.x == 0) {
        float lse = m + logf(s);
        float nll = lse - lr[targets[row]];
        atomicAdd(loss, nll * invN);
    }
}

// ---------------- launch ----------------
extern "C" void kernel_launch(void* const* d_in, const int* in_sizes, int n_in,
                              void* d_out, int out_size) {
    const int* tokens = (const int*)d_in[0];
    const int* targets = (const int*)d_in[1];
    const float* tok_emb = (const float*)d_in[2];
    const float* pos_emb = (const float*)d_in[3];
    const float* Wq = (const float*)d_in[4];
    const float* Wk = (const float*)d_in[5];
    const float* Wv = (const float*)d_in[6];
    const float* Wo = (const float*)d_in[7];
    const float* bo = (const float*)d_in[8];
    const float* ln1_g = (const float*)d_in[9];
    const float* ln1_b = (const float*)d_in[10];
    const float* ln2_g = (const float*)d_in[11];
    const float* ln2_b = (const float*)d_in[12];
    const float* W1 = (const float*)d_in[13];
    const float* b1 = (const float*)d_in[14];
    const float* W2 = (const float*)d_in[15];
    const float* b2 = (const float*)d_in[16];
    const float* lnf_g = (const float*)d_in[17];
    const float* lnf_b = (const float*)d_in[18];
    const float* Wout = (const float*)d_in[19];
    const float* bout = (const float*)d_in[20];
    float* out = (float*)d_out;

    // idempotent, cheap; needed for 64KB dynamic smem
    cudaFuncSetAttribute(mma_gemm_kernel<0>, cudaFuncAttributeMaxDynamicSharedMemorySize, TCG_SMEM);
    cudaFuncSetAttribute(mma_gemm_kernel<1>, cudaFuncAttributeMaxDynamicSharedMemorySize, TCG_SMEM);
    cudaFuncSetAttribute(mma_gemm_kernel<2>, cudaFuncAttributeMaxDynamicSharedMemorySize, TCG_SMEM);
    cudaFuncSetAttribute(mma_gemm_kernel<3>, cudaFuncAttributeMaxDynamicSharedMemorySize, TCG_SMEM);

    float *h, *xn, *qkv, *o, *ff;
    __nv_bfloat16 *abig, *bqkv, *bwo, *bw1, *bw2, *bwout;
    cudaGetSymbolAddress((void**)&h, g_h);
    cudaGetSymbolAddress((void**)&xn, g_xn);
    cudaGetSymbolAddress((void**)&qkv, g_qkv);
    cudaGetSymbolAddress((void**)&o, g_o);
    cudaGetSymbolAddress((void**)&ff, g_ff);
    cudaGetSymbolAddress((void**)&abig, g_abig);
    cudaGetSymbolAddress((void**)&bqkv, g_bqkv);
    cudaGetSymbolAddress((void**)&bwo, g_bwo);
    cudaGetSymbolAddress((void**)&bw1, g_bw1);
    cudaGetSymbolAddress((void**)&bw2, g_bw2);
    cudaGetSymbolAddress((void**)&bwout, g_bwout);

    // ---- weight prep: transpose to [N,K] and bf16x3 split ----
    dim3 tb(32, 8);
    transpose_split_kernel<<<dim3(2, 32, L_ * H_), tb>>>(Wq, bqkv, D_, DH_, (long)D_ * DH_, (long)K3D * K3D, H_, 0, K3D);
    transpose_split_kernel<<<dim3(2, 32, L_ * H_), tb>>>(Wk, bqkv, D_, DH_, (long)D_ * DH_, (long)K3D * K3D, H_, D_, K3D);
    transpose_split_kernel<<<dim3(2, 32, L_ * H_), tb>>>(Wv, bqkv, D_, DH_, (long)D_ * DH_, (long)K3D * K3D, H_, 2 * D_, K3D);
    transpose_split_kernel<<<dim3(32, 32, L_), tb>>>(Wo, bwo, D_, D_, (long)D_ * D_, (long)D_ * K3D, 1, 0, K3D);
    transpose_split_kernel<<<dim3(128, 32, L_), tb>>>(W1, bw1, D_, FF_, (long)D_ * FF_, (long)FF_ * K3D, 1, 0, K3D);
    transpose_split_kernel<<<dim3(32, 128, L_), tb>>>(W2, bw2, FF_, D_, (long)FF_ * D_, (long)D_ * K3F, 1, 0, K3F);
    transpose_split_kernel<<<dim3(1000, 32, 1), tb>>>(Wout, bwout, D_, V_, 0, 0, 1, 0, K3D);

    embed_kernel<<<(BS_ * D_ + 255) / 256, 256>>>(tokens, tok_emb, pos_emb, h);

    for (int l = 0; l < L_; l++) {
        layernorm_kernel<<<BS_, 256>>>(h, ln1_g + (size_t)l * D_, ln1_b + (size_t)l * D_, xn);
        act_split_kernel<<<BS_ * D_ / 256, 256>>>(xn, abig, D_);
        run_tc(abig, bqkv + (size_t)l * K3D * K3D, nullptr, nullptr, qkv, K3D, K3D, 0);
        dim3 ag(S_, H_, B_);
        attention_kernel<<<ag, 128>>>(qkv, o);
        act_split_kernel<<<BS_ * D_ / 256, 256>>>(o, abig, D_);
        run_tc(abig, bwo + (size_t)l * D_ * K3D, bo + (size_t)l * D_, h, h, D_, K3D, 2);
        layernorm_kernel<<<BS_, 256>>>(h, ln2_g + (size_t)l * D_, ln2_b + (size_t)l * D_, xn);
        act_split_kernel<<<BS_ * D_ / 256, 256>>>(xn, abig, D_);
        run_tc(abig, bw1 + (size_t)l * FF_ * K3D, b1 + (size_t)l * FF_, nullptr, ff, FF_, K3D, 3);
        act_split_kernel<<<BS_ * FF_ / 256, 256>>>(ff, abig, FF_);
        run_tc(abig, bw2 + (size_t)l * D_ * K3F, b2 + (size_t)l * D_, h, h, D_, K3F, 2);
    }

    layernorm_kernel<<<BS_, 256>>>(h, lnf_g, lnf_b, xn);
    act_split_kernel<<<BS_ * D_ / 256, 256>>>(xn, abig, D_);
    run_tc(abig, bwout, bout, nullptr, out, V_, K3D, 1);

    long long BSV = (long long)BS_ * V_;
    if ((long long)out_size > BSV) {
        zero_kernel<<<1, 1>>>(out + BSV);
        loss_kernel<<<BS_, 256>>>(out, targets, out + BSV, 1.0f / BS_);
    }
}

// round 4
// speedup vs baseline: 1.3398x; 1.0311x over previous
#include <cuda_runtime.h>
#include <cuda_bf16.h>
#include <cstdint>
#include <math.h>

// Problem constants
#define B_ 2
#define S_ 1024
#define D_ 1024
#define H_ 16
#define DH_ 64
#define L_ 8
#define FF_ 4096
#define V_ 32000
#define BS_ (B_ * S_)
#define K3D (3 * D_)    // 3072
#define K3F (3 * FF_)   // 12288

// ---------------- scratch (device globals) ----------------
__device__ float g_h[BS_ * D_];
__device__ float g_xn[BS_ * D_];
__device__ float g_qkv[BS_ * K3D];
__device__ float g_o[BS_ * D_];
__device__ float g_ff[BS_ * FF_];
__device__ __nv_bfloat16 g_abig[BS_ * K3F];
__device__ __nv_bfloat16 g_bqkv[(size_t)L_ * K3D * K3D];
__device__ __nv_bfloat16 g_bwo[(size_t)L_ * D_ * K3D];
__device__ __nv_bfloat16 g_bw1[(size_t)L_ * FF_ * K3D];
__device__ __nv_bfloat16 g_bw2[(size_t)L_ * D_ * K3F];
__device__ __nv_bfloat16 g_bwout[(size_t)V_ * K3D];

// ---------------- helpers ----------------
__device__ __forceinline__ uint32_t smem_u32(const void* p) {
    uint32_t a;
    asm("{ .reg .u64 t; cvta.to.shared.u64 t, %1; cvt.u32.u64 %0, t; }" : "=r"(a) : "l"(p));
    return a;
}
__device__ __forceinline__ void cp_async16(uint32_t dst, const void* src) {
    asm volatile("cp.async.cg.shared.global [%0], [%1], 16;" :: "r"(dst), "l"(src) : "memory");
}
__device__ __forceinline__ void cp_commit() {
    asm volatile("cp.async.commit_group;" ::: "memory");
}
template <int N>
__device__ __forceinline__ void cp_wait() {
    asm volatile("cp.async.wait_group %0;" :: "n"(N) : "memory");
}
__device__ __forceinline__ void ldmatrix_x4(uint32_t* r, uint32_t addr) {
    asm volatile("ldmatrix.sync.aligned.m8n8.x4.shared.b16 {%0,%1,%2,%3}, [%4];"
                 : "=r"(r[0]), "=r"(r[1]), "=r"(r[2]), "=r"(r[3]) : "r"(addr));
}
__device__ __forceinline__ void mma16816(float* c, const uint32_t* a, uint32_t b0, uint32_t b1) {
    asm volatile(
        "mma.sync.aligned.m16n8k16.row.col.f32.bf16.bf16.f32 "
        "{%0,%1,%2,%3}, {%4,%5,%6,%7}, {%8,%9}, {%0,%1,%2,%3};"
        : "+f"(c[0]), "+f"(c[1]), "+f"(c[2]), "+f"(c[3])
        : "r"(a[0]), "r"(a[1]), "r"(a[2]), "r"(a[3]), "r"(b0), "r"(b1));
}

// ---------------- reductions ----------------
__device__ __forceinline__ float warpReduceSum(float v) {
    #pragma unroll
    for (int o = 16; o > 0; o >>= 1) v += __shfl_xor_sync(0xffffffffu, v, o);
    return v;
}
__device__ __forceinline__ float warpReduceMax(float v) {
    #pragma unroll
    for (int o = 16; o > 0; o >>= 1) v = fmaxf(v, __shfl_xor_sync(0xffffffffu, v, o));
    return v;
}
__device__ float blockReduceSum(float v) {
    __shared__ float sh[33];
    __syncthreads();
    int lane = threadIdx.x & 31, w = threadIdx.x >> 5;
    v = warpReduceSum(v);
    if (lane == 0) sh[w] = v;
    __syncthreads();
    int nw = (blockDim.x + 31) >> 5;
    float r = (threadIdx.x < nw) ? sh[threadIdx.x] : 0.0f;
    if (w == 0) { r = warpReduceSum(r); if (lane == 0) sh[32] = r; }
    __syncthreads();
    return sh[32];
}
__device__ float blockReduceMax(float v) {
    __shared__ float sh[33];
    __syncthreads();
    int lane = threadIdx.x & 31, w = threadIdx.x >> 5;
    v = warpReduceMax(v);
    if (lane == 0) sh[w] = v;
    __syncthreads();
    int nw = (blockDim.x + 31) >> 5;
    float r = (threadIdx.x < nw) ? sh[threadIdx.x] : -3.0e38f;
    if (w == 0) { r = warpReduceMax(r); if (lane == 0) sh[32] = r; }
    __syncthreads();
    return sh[32];
}

// ---------------- weight transpose + bf16x3 split -----------------
__global__ void transpose_split_kernel(const float* __restrict__ W, __nv_bfloat16* __restrict__ out,
                                       int K, int N, long in_z_stride, long out_l_stride,
                                       int h_group, int row_off, int Kp) {
    int z = blockIdx.z;
    int l = z / h_group, h = z % h_group;
    const float* Win = W + (long)z * in_z_stride;
    __nv_bfloat16* O = out + (long)l * out_l_stride;
    int base_row = row_off + h * N;
    __shared__ float t[32][33];
    int kb = blockIdx.y * 32, nb = blockIdx.x * 32;
    #pragma unroll
    for (int j = 0; j < 4; j++) {
        int r = threadIdx.y + j * 8;
        int k = kb + r, n = nb + threadIdx.x;
        t[r][threadIdx.x] = (k < K && n < N) ? Win[(long)k * N + n] : 0.0f;
    }
    __syncthreads();
    #pragma unroll
    for (int j = 0; j < 4; j++) {
        int r = threadIdx.y + j * 8;
        int n = nb + r, k = kb + threadIdx.x;
        if (n < N && k < K) {
            float w = t[threadIdx.x][r];
            __nv_bfloat16 hi = __float2bfloat16(w);
            __nv_bfloat16 lo = __float2bfloat16(w - __bfloat162float(hi));
            long ro = (long)(base_row + n) * Kp;
            O[ro + k] = hi;
            O[ro + K + k] = lo;
            O[ro + 2 * K + k] = hi;
        }
    }
}

// Activation split: A[M,K] fp32 -> [hi | hi | lo] bf16 [M, 3K]
__global__ void act_split_kernel(const float* __restrict__ A, __nv_bfloat16* __restrict__ out, int K) {
    long i = (long)blockIdx.x * 256 + threadIdx.x;
    int k = (int)(i % K);
    long m = i / K;
    float w = A[i];
    __nv_bfloat16 hi = __float2bfloat16(w);
    __nv_bfloat16 lo = __float2bfloat16(w - __bfloat162float(hi));
    long ro = m * (long)(3 * K);
    out[ro + k] = hi;
    out[ro + K + k] = hi;
    out[ro + 2 * K + k] = lo;
}

// ---------------- mma.sync GEMM: C[M,N] = A[M,K'] * B[N,K']^T ----------------
// 128x128 CTA tile, BK=64, 3-stage cp.async pipeline, 2 CTAs/SM.
// 8 warps: 4 (M) x 2 (N); warp tile 32x64. MODE: 0 none,1 bias,2 bias+resid,3 bias+relu
#define STAGES 3
#define TCG_SMEM (STAGES * 32768)
template <int MODE>
__global__ __launch_bounds__(256, 2) void mma_gemm_kernel(
    const __nv_bfloat16* __restrict__ A, const __nv_bfloat16* __restrict__ Bw,
    const float* __restrict__ bias, const float* __restrict__ resid,
    float* __restrict__ C, int N, int K3) {
    extern __shared__ char sm[];
    uint32_t smb = smem_u32(sm);

    int tid = threadIdx.x, lane = tid & 31, wid = tid >> 5;
    int wm = wid & 3;    // m offset 32*wm
    int wn = wid >> 2;   // n offset 64*wn
    int row0 = blockIdx.y * 128, col0 = blockIdx.x * 128;

    const char* Ab = (const char*)A;
    const char* Bb = (const char*)Bw;
    long strideB = (long)K3 * 2;

    int nc = K3 >> 6;

    auto load_chunk = [&](int c, int s) {
        long kcb = (long)c * 128;
        uint32_t bA = smb + (uint32_t)s * 32768u;
        uint32_t bB = bA + 16384u;
        #pragma unroll
        for (int j = 0; j < 4; j++) {
            int i = tid + j * 256;
            int r = i >> 3;
            uint32_t cb = (uint32_t)(i & 7) * 16;
            uint32_t off = (uint32_t)r * 128 + cb;
            uint32_t sw = off ^ ((off >> 3) & 0x70);
            cp_async16(bA + sw, Ab + (long)(row0 + r) * strideB + kcb + cb);
            cp_async16(bB + sw, Bb + (long)(col0 + r) * strideB + kcb + cb);
        }
        cp_commit();
    };

    float acc[2][8][4];
    #pragma unroll
    for (int i = 0; i < 2; i++)
        #pragma unroll
        for (int j = 0; j < 8; j++)
            #pragma unroll
            for (int k = 0; k < 4; k++) acc[i][j][k] = 0.0f;

    // prologue: fill STAGES-1 stages
    #pragma unroll
    for (int s = 0; s < STAGES - 1; s++)
        if (s < nc) load_chunk(s, s);

    for (int c = 0; c < nc; c++) {
        if (c + 1 < nc) cp_wait<STAGES - 2>();
        else cp_wait<0>();
        __syncthreads();
        // issue next load into the stage freed by iteration c-1
        int nxt = c + STAGES - 1;
        if (nxt < nc) load_chunk(nxt, nxt % STAGES);

        int st = c % STAGES;
        uint32_t bufA = smb + (uint32_t)st * 32768u;
        uint32_t bufB = bufA + 16384u;

        #pragma unroll
        for (int s = 0; s < 4; s++) {
            int kb = s * 32 + (lane >> 4) * 16;
            uint32_t aF[2][4], bF[4][4];
            #pragma unroll
            for (int fm = 0; fm < 2; fm++) {
                uint32_t off = (uint32_t)(wm * 32 + fm * 16 + (lane & 15)) * 128 + kb;
                ldmatrix_x4(aF[fm], bufA + (off ^ ((off >> 3) & 0x70)));
            }
            #pragma unroll
            for (int fb = 0; fb < 4; fb++) {
                uint32_t off = (uint32_t)(wn * 64 + fb * 16 + (lane & 15)) * 128 + kb;
                ldmatrix_x4(bF[fb], bufB + (off ^ ((off >> 3) & 0x70)));
            }
            #pragma unroll
            for (int fm = 0; fm < 2; fm++)
                #pragma unroll
                for (int fn = 0; fn < 8; fn++) {
                    int fb = fn >> 1, odd = fn & 1;
                    mma16816(acc[fm][fn], aF[fm], bF[fb][odd], bF[fb][odd + 2]);
                }
        }
    }

    // epilogue: direct register -> global with fused ops
    #pragma unroll
    for (int fm = 0; fm < 2; fm++) {
        #pragma unroll
        for (int fn = 0; fn < 8; fn++) {
            int gr = row0 + wm * 32 + fm * 16 + (lane >> 2);
            int gc = col0 + wn * 64 + fn * 8 + 2 * (lane & 3);
            float v0 = acc[fm][fn][0], v1 = acc[fm][fn][1];
            float v2 = acc[fm][fn][2], v3 = acc[fm][fn][3];
            if (MODE >= 1) {
                float b0 = bias[gc], b1 = bias[gc + 1];
                v0 += b0; v1 += b1; v2 += b0; v3 += b1;
            }
            if (MODE == 2) {
                v0 += resid[(long)gr * N + gc];
                v1 += resid[(long)gr * N + gc + 1];
                v2 += resid[(long)(gr + 8) * N + gc];
                v3 += resid[(long)(gr + 8) * N + gc + 1];
            }
            if (MODE == 3) {
                v0 = fmaxf(v0, 0.0f); v1 = fmaxf(v1, 0.0f);
                v2 = fmaxf(v2, 0.0f); v3 = fmaxf(v3, 0.0f);
            }
            *(float2*)&C[(long)gr * N + gc] = make_float2(v0, v1);
            *(float2*)&C[(long)(gr + 8) * N + gc] = make_float2(v2, v3);
        }
    }
}

static void run_tc(const __nv_bfloat16* A, const __nv_bfloat16* B, const float* bias,
                   const float* resid, float* C, int N, int K3, int mode) {
    dim3 grid(N / 128, BS_ / 128);
    if (mode == 0) mma_gemm_kernel<0><<<grid, 256, TCG_SMEM>>>(A, B, bias, resid, C, N, K3);
    else if (mode == 1) mma_gemm_kernel<1><<<grid, 256, TCG_SMEM>>>(A, B, bias, resid, C, N, K3);
    else if (mode == 2) mma_gemm_kernel<2><<<grid, 256, TCG_SMEM>>>(A, B, bias, resid, C, N, K3);
    else mma_gemm_kernel<3><<<grid, 256, TCG_SMEM>>>(A, B, bias, resid, C, N, K3);
}

// ---------------- embedding ----------------
__global__ void embed_kernel(const int* __restrict__ tokens,
                             const float* __restrict__ tok_emb,
                             const float* __restrict__ pos_emb,
                             float* __restrict__ h) {
    int i = blockIdx.x * blockDim.x + threadIdx.x;
    if (i >= BS_ * D_) return;
    int d = i % D_;
    int bs = i / D_;
    int s = bs % S_;
    int tok = tokens[bs];
    h[i] = tok_emb[(size_t)tok * D_ + d] + pos_emb[(size_t)s * D_ + d];
}

// ---------------- layernorm ----------------
__global__ void layernorm_kernel(const float* __restrict__ x,
                                 const float* __restrict__ g,
                                 const float* __restrict__ b,
                                 float* __restrict__ y) {
    int row = blockIdx.x;
    const float* xr = x + (size_t)row * D_;
    float* yr = y + (size_t)row * D_;
    float vals[4];
    float s = 0.0f;
    #pragma unroll
    for (int j = 0; j < 4; j++) { vals[j] = xr[threadIdx.x + j * 256]; s += vals[j]; }
    float mean = blockReduceSum(s) * (1.0f / D_);
    float var = 0.0f;
    #pragma unroll
    for (int j = 0; j < 4; j++) { float d = vals[j] - mean; var += d * d; }
    var = blockReduceSum(var) * (1.0f / D_);
    float rstd = rsqrtf(var + 1e-5f);
    #pragma unroll
    for (int j = 0; j < 4; j++) {
        int i = threadIdx.x + j * 256;
        yr[i] = (vals[j] - mean) * rstd * g[i] + b[i];
    }
}

// ---------------- fused causal attention (QKV packed [bs][3072]) -----------
__global__ __launch_bounds__(128) void attention_kernel(const float* __restrict__ QKV,
                                                        float* __restrict__ O) {
    int q = blockIdx.x, h = blockIdx.y, b = blockIdx.z;
    const float scale = 0.03125f;  // D^-0.5 (reference scales by embedding dim)
    __shared__ float sQ[DH_];
    __shared__ float sS[S_];
    __shared__ float sAcc[128];
    int tid = threadIdx.x;
    size_t qrow = ((size_t)(b * S_ + q)) * K3D + h * DH_;
    if (tid < DH_) sQ[tid] = QKV[qrow + tid];
    __syncthreads();

    int nk = q + 1;
    float lmax = -3.0e38f;
    for (int k = tid; k < nk; k += 128) {
        const float* kr = QKV + ((size_t)(b * S_ + k)) * K3D + D_ + h * DH_;
        float s = 0.0f;
        #pragma unroll
        for (int e = 0; e < DH_; e++) s = fmaf(sQ[e], kr[e], s);
        s *= scale;
        sS[k] = s;
        lmax = fmaxf(lmax, s);
    }
    float m = blockReduceMax(lmax);
    float lsum = 0.0f;
    for (int k = tid; k < nk; k += 128) {
        float p = expf(sS[k] - m);
        sS[k] = p;
        lsum += p;
    }
    float denom = blockReduceSum(lsum);
    float inv = 1.0f / denom;

    int e = tid & 63, half = tid >> 6;
    float acc = 0.0f;
    for (int k = half; k < nk; k += 2)
        acc = fmaf(sS[k], QKV[((size_t)(b * S_ + k)) * K3D + 2 * D_ + h * DH_ + e], acc);
    sAcc[tid] = acc;
    __syncthreads();
    if (tid < DH_) O[((size_t)(b * S_ + q)) * D_ + h * DH_ + tid] = (sAcc[tid] + sAcc[tid + 64]) * inv;
}

// ---------------- loss ----------------
__global__ void zero_kernel(float* p) { *p = 0.0f; }

__global__ void loss_kernel(const float* __restrict__ logits,
                            const int* __restrict__ targets,
                            float* __restrict__ loss, float invN) {
    int row = blockIdx.x;
    const float* lr = logits + (size_t)row * V_;
    float lmax = -3.0e38f;
    for (int i = threadIdx.x; i < V_; i += blockDim.x) lmax = fmaxf(lmax, lr[i]);
    float m = blockReduceMax(lmax);
    float lsum = 0.0f;
    for (int i = threadIdx.x; i < V_; i += blockDim.x) lsum += expf(lr[i] - m);
    float s = blockReduceSum(lsum);
    if (threadIdx.x == 0) {
        float lse = m + logf(s);
        float nll = lse - lr[targets[row]];
        atomicAdd(loss, nll * invN);
    }
}

// ---------------- launch ----------------
extern "C" void kernel_launch(void* const* d_in, const int* in_sizes, int n_in,
                              void* d_out, int out_size) {
    const int* tokens = (const int*)d_in[0];
    const int* targets = (const int*)d_in[1];
    const float* tok_emb = (const float*)d_in[2];
    const float* pos_emb = (const float*)d_in[3];
    const float* Wq = (const float*)d_in[4];
    const float* Wk = (const float*)d_in[5];
    const float* Wv = (const float*)d_in[6];
    const float* Wo = (const float*)d_in[7];
    const float* bo = (const float*)d_in[8];
    const float* ln1_g = (const float*)d_in[9];
    const float* ln1_b = (const float*)d_in[10];
    const float* ln2_g = (const float*)d_in[11];
    const float* ln2_b = (const float*)d_in[12];
    const float* W1 = (const float*)d_in[13];
    const float* b1 = (const float*)d_in[14];
    const float* W2 = (const float*)d_in[15];
    const float* b2 = (const float*)d_in[16];
    const float* lnf_g = (const float*)d_in[17];
    const float* lnf_b = (const float*)d_in[18];
    const float* Wout = (const float*)d_in[19];
    const float* bout = (const float*)d_in[20];
    float* out = (float*)d_out;

    cudaFuncSetAttribute(mma_gemm_kernel<0>, cudaFuncAttributeMaxDynamicSharedMemorySize, TCG_SMEM);
    cudaFuncSetAttribute(mma_gemm_kernel<1>, cudaFuncAttributeMaxDynamicSharedMemorySize, TCG_SMEM);
    cudaFuncSetAttribute(mma_gemm_kernel<2>, cudaFuncAttributeMaxDynamicSharedMemorySize, TCG_SMEM);
    cudaFuncSetAttribute(mma_gemm_kernel<3>, cudaFuncAttributeMaxDynamicSharedMemorySize, TCG_SMEM);

    float *h, *xn, *qkv, *o, *ff;
    __nv_bfloat16 *abig, *bqkv, *bwo, *bw1, *bw2, *bwout;
    cudaGetSymbolAddress((void**)&h, g_h);
    cudaGetSymbolAddress((void**)&xn, g_xn);
    cudaGetSymbolAddress((void**)&qkv, g_qkv);
    cudaGetSymbolAddress((void**)&o, g_o);
    cudaGetSymbolAddress((void**)&ff, g_ff);
    cudaGetSymbolAddress((void**)&abig, g_abig);
    cudaGetSymbolAddress((void**)&bqkv, g_bqkv);
    cudaGetSymbolAddress((void**)&bwo, g_bwo);
    cudaGetSymbolAddress((void**)&bw1, g_bw1);
    cudaGetSymbolAddress((void**)&bw2, g_bw2);
    cudaGetSymbolAddress((void**)&bwout, g_bwout);

    // ---- weight prep: transpose to [N,K] and bf16x3 split ----
    dim3 tb(32, 8);
    transpose_split_kernel<<<dim3(2, 32, L_ * H_), tb>>>(Wq, bqkv, D_, DH_, (long)D_ * DH_, (long)K3D * K3D, H_, 0, K3D);
    transpose_split_kernel<<<dim3(2, 32, L_ * H_), tb>>>(Wk, bqkv, D_, DH_, (long)D_ * DH_, (long)K3D * K3D, H_, D_, K3D);
    transpose_split_kernel<<<dim3(2, 32, L_ * H_), tb>>>(Wv, bqkv, D_, DH_, (long)D_ * DH_, (long)K3D * K3D, H_, 2 * D_, K3D);
    transpose_split_kernel<<<dim3(32, 32, L_), tb>>>(Wo, bwo, D_, D_, (long)D_ * D_, (long)D_ * K3D, 1, 0, K3D);
    transpose_split_kernel<<<dim3(128, 32, L_), tb>>>(W1, bw1, D_, FF_, (long)D_ * FF_, (long)FF_ * K3D, 1, 0, K3D);
    transpose_split_kernel<<<dim3(32, 128, L_), tb>>>(W2, bw2, FF_, D_, (long)FF_ * D_, (long)D_ * K3F, 1, 0, K3F);
    transpose_split_kernel<<<dim3(1000, 32, 1), tb>>>(Wout, bwout, D_, V_, 0, 0, 1, 0, K3D);

    embed_kernel<<<(BS_ * D_ + 255) / 256, 256>>>(tokens, tok_emb, pos_emb, h);

    for (int l = 0; l < L_; l++) {
        layernorm_kernel<<<BS_, 256>>>(h, ln1_g + (size_t)l * D_, ln1_b + (size_t)l * D_, xn);
        act_split_kernel<<<BS_ * D_ / 256, 256>>>(xn, abig, D_);
        run_tc(abig, bqkv + (size_t)l * K3D * K3D, nullptr, nullptr, qkv, K3D, K3D, 0);
        dim3 ag(S_, H_, B_);
        attention_kernel<<<ag, 128>>>(qkv, o);
        act_split_kernel<<<BS_ * D_ / 256, 256>>>(o, abig, D_);
        run_tc(abig, bwo + (size_t)l * D_ * K3D, bo + (size_t)l * D_, h, h, D_, K3D, 2);
        layernorm_kernel<<<BS_, 256>>>(h, ln2_g + (size_t)l * D_, ln2_b + (size_t)l * D_, xn);
        act_split_kernel<<<BS_ * D_ / 256, 256>>>(xn, abig, D_);
        run_tc(abig, bw1 + (size_t)l * FF_ * K3D, b1 + (size_t)l * FF_, nullptr, ff, FF_, K3D, 3);
        act_split_kernel<<<BS_ * FF_ / 256, 256>>>(ff, abig, FF_);
        run_tc(abig, bw2 + (size_t)l * D_ * K3F, b2 + (size_t)l * D_, h, h, D_, K3F, 2);
    }

    layernorm_kernel<<<BS_, 256>>>(h, lnf_g, lnf_b, xn);
    act_split_kernel<<<BS_ * D_ / 256, 256>>>(xn, abig, D_);
    run_tc(abig, bwout, bout, nullptr, out, V_, K3D, 1);

    long long BSV = (long long)BS_ * V_;
    if ((long long)out_size > BSV) {
        zero_kernel<<<1, 1>>>(out + BSV);
        loss_kernel<<<BS_, 256>>>(out, targets, out + BSV, 1.0f / BS_);
    }
}

// round 5
// speedup vs baseline: 4.7526x; 3.5474x over previous
#include <cuda_runtime.h>
#include <cuda_bf16.h>
#include <cstdint>
#include <math.h>

// Problem constants
#define B_ 2
#define S_ 1024
#define D_ 1024
#define H_ 16
#define DH_ 64
#define L_ 8
#define FF_ 4096
#define V_ 32000
#define BS_ (B_ * S_)
#define K3D (3 * D_)    // 3072
#define K3F (3 * FF_)   // 12288

// ---------------- scratch (device globals) ----------------
__device__ float g_h[BS_ * D_];
__device__ float g_xn[BS_ * D_];
__device__ float g_qkv[BS_ * K3D];
__device__ float g_o[BS_ * D_];
__device__ float g_ff[BS_ * FF_];
__device__ __nv_bfloat16 g_abig[BS_ * K3F];
__device__ __nv_bfloat16 g_bqkv[(size_t)L_ * K3D * K3D];
__device__ __nv_bfloat16 g_bwo[(size_t)L_ * D_ * K3D];
__device__ __nv_bfloat16 g_bw1[(size_t)L_ * FF_ * K3D];
__device__ __nv_bfloat16 g_bw2[(size_t)L_ * D_ * K3F];
__device__ __nv_bfloat16 g_bwout[(size_t)V_ * K3D];

// ---------------- helpers ----------------
__device__ __forceinline__ uint32_t smem_u32(const void* p) {
    uint32_t a;
    asm("{ .reg .u64 t; cvta.to.shared.u64 t, %1; cvt.u32.u64 %0, t; }" : "=r"(a) : "l"(p));
    return a;
}
__device__ __forceinline__ void cp_async16(uint32_t dst, const void* src) {
    asm volatile("cp.async.cg.shared.global [%0], [%1], 16;" :: "r"(dst), "l"(src) : "memory");
}
__device__ __forceinline__ void cp_commit() {
    asm volatile("cp.async.commit_group;" ::: "memory");
}
template <int N>
__device__ __forceinline__ void cp_wait() {
    asm volatile("cp.async.wait_group %0;" :: "n"(N) : "memory");
}
__device__ __forceinline__ void ldmatrix_x4(uint32_t* r, uint32_t addr) {
    asm volatile("ldmatrix.sync.aligned.m8n8.x4.shared.b16 {%0,%1,%2,%3}, [%4];"
                 : "=r"(r[0]), "=r"(r[1]), "=r"(r[2]), "=r"(r[3]) : "r"(addr));
}
__device__ __forceinline__ void mma16816(float* c, const uint32_t* a, uint32_t b0, uint32_t b1) {
    asm volatile(
        "mma.sync.aligned.m16n8k16.row.col.f32.bf16.bf16.f32 "
        "{%0,%1,%2,%3}, {%4,%5,%6,%7}, {%8,%9}, {%0,%1,%2,%3};"
        : "+f"(c[0]), "+f"(c[1]), "+f"(c[2]), "+f"(c[3])
        : "r"(a[0]), "r"(a[1]), "r"(a[2]), "r"(a[3]), "r"(b0), "r"(b1));
}

// ---------------- reductions ----------------
__device__ __forceinline__ float warpReduceSum(float v) {
    #pragma unroll
    for (int o = 16; o > 0; o >>= 1) v += __shfl_xor_sync(0xffffffffu, v, o);
    return v;
}
__device__ __forceinline__ float warpReduceMax(float v) {
    #pragma unroll
    for (int o = 16; o > 0; o >>= 1) v = fmaxf(v, __shfl_xor_sync(0xffffffffu, v, o));
    return v;
}
__device__ float blockReduceSum(float v) {
    __shared__ float sh[33];
    __syncthreads();
    int lane = threadIdx.x & 31, w = threadIdx.x >> 5;
    v = warpReduceSum(v);
    if (lane == 0) sh[w] = v;
    __syncthreads();
    int nw = (blockDim.x + 31) >> 5;
    float r = (threadIdx.x < nw) ? sh[threadIdx.x] : 0.0f;
    if (w == 0) { r = warpReduceSum(r); if (lane == 0) sh[32] = r; }
    __syncthreads();
    return sh[32];
}
__device__ float blockReduceMax(float v) {
    __shared__ float sh[33];
    __syncthreads();
    int lane = threadIdx.x & 31, w = threadIdx.x >> 5;
    v = warpReduceMax(v);
    if (lane == 0) sh[w] = v;
    __syncthreads();
    int nw = (blockDim.x + 31) >> 5;
    float r = (threadIdx.x < nw) ? sh[threadIdx.x] : -3.0e38f;
    if (w == 0) { r = warpReduceMax(r); if (lane == 0) sh[32] = r; }
    __syncthreads();
    return sh[32];
}

// ---------------- weight transpose + bf16x3 split -----------------
__global__ void transpose_split_kernel(const float* __restrict__ W, __nv_bfloat16* __restrict__ out,
                                       int K, int N, long in_z_stride, long out_l_stride,
                                       int h_group, int row_off, int Kp) {
    int z = blockIdx.z;
    int l = z / h_group, h = z % h_group;
    const float* Win = W + (long)z * in_z_stride;
    __nv_bfloat16* O = out + (long)l * out_l_stride;
    int base_row = row_off + h * N;
    __shared__ float t[32][33];
    int kb = blockIdx.y * 32, nb = blockIdx.x * 32;
    #pragma unroll
    for (int j = 0; j < 4; j++) {
        int r = threadIdx.y + j * 8;
        int k = kb + r, n = nb + threadIdx.x;
        t[r][threadIdx.x] = (k < K && n < N) ? Win[(long)k * N + n] : 0.0f;
    }
    __syncthreads();
    #pragma unroll
    for (int j = 0; j < 4; j++) {
        int r = threadIdx.y + j * 8;
        int n = nb + r, k = kb + threadIdx.x;
        if (n < N && k < K) {
            float w = t[threadIdx.x][r];
            __nv_bfloat16 hi = __float2bfloat16(w);
            __nv_bfloat16 lo = __float2bfloat16(w - __bfloat162float(hi));
            long ro = (long)(base_row + n) * Kp;
            O[ro + k] = hi;
            O[ro + K + k] = lo;
            O[ro + 2 * K + k] = hi;
        }
    }
}

// Activation split: A[M,K] fp32 -> [hi | hi | lo] bf16 [M, 3K]
__global__ void act_split_kernel(const float* __restrict__ A, __nv_bfloat16* __restrict__ out, int K) {
    long i = (long)blockIdx.x * 256 + threadIdx.x;
    int k = (int)(i % K);
    long m = i / K;
    float w = A[i];
    __nv_bfloat16 hi = __float2bfloat16(w);
    __nv_bfloat16 lo = __float2bfloat16(w - __bfloat162float(hi));
    long ro = m * (long)(3 * K);
    out[ro + k] = hi;
    out[ro + K + k] = hi;
    out[ro + 2 * K + k] = lo;
}

// ---------------- mma.sync GEMM: C[M,N] = A[M,K'] * B[N,K']^T ----------------
// Template: BM in {64,128}; CTA tile BM x 128, BK=64, 3-stage cp.async pipeline.
// BM=128: 8 warps 4x2, warp tile 32x64. BM=64: 8 warps 2x4, warp tile 32x32.
// MODE: 0 none,1 bias,2 bias+resid,3 bias+relu
#define STAGES 3
template <int BM, int MODE>
__global__ __launch_bounds__(256, 2) void mma_gemm_kernel(
    const __nv_bfloat16* __restrict__ A, const __nv_bfloat16* __restrict__ Bw,
    const float* __restrict__ bias, const float* __restrict__ resid,
    float* __restrict__ C, int N, int K3) {
    constexpr int WMN = (BM == 128) ? 4 : 2;     // warps along M
    constexpr int WNT = (BM == 128) ? 64 : 32;   // warp tile N
    constexpr int FB = WNT / 16;                 // b-frag groups
    constexpr int FN = 2 * FB;                   // n-frags of 8
    constexpr int ABYTES = BM * 128;
    constexpr int STAGE = ABYTES + 16384;
    constexpr int AITER = BM / 32;               // A load iterations

    extern __shared__ char sm[];
    uint32_t smb = smem_u32(sm);

    int tid = threadIdx.x, lane = tid & 31, wid = tid >> 5;
    int wm = wid % WMN;
    int wn = wid / WMN;
    int row0 = blockIdx.y * BM, col0 = blockIdx.x * 128;

    const char* Ab = (const char*)A;
    const char* Bb = (const char*)Bw;
    long strideB = (long)K3 * 2;

    int nc = K3 >> 6;

    auto load_chunk = [&](int c, int s) {
        long kcb = (long)c * 128;
        uint32_t bA = smb + (uint32_t)s * STAGE;
        uint32_t bB = bA + ABYTES;
        #pragma unroll
        for (int j = 0; j < AITER; j++) {
            int i = tid + j * 256;
            int r = i >> 3;
            uint32_t cb = (uint32_t)(i & 7) * 16;
            uint32_t off = (uint32_t)r * 128 + cb;
            uint32_t sw = off ^ ((off >> 3) & 0x70);
            cp_async16(bA + sw, Ab + (long)(row0 + r) * strideB + kcb + cb);
        }
        #pragma unroll
        for (int j = 0; j < 4; j++) {
            int i = tid + j * 256;
            int r = i >> 3;
            uint32_t cb = (uint32_t)(i & 7) * 16;
            uint32_t off = (uint32_t)r * 128 + cb;
            uint32_t sw = off ^ ((off >> 3) & 0x70);
            cp_async16(bB + sw, Bb + (long)(col0 + r) * strideB + kcb + cb);
        }
        cp_commit();
    };

    float acc[2][FN][4];
    #pragma unroll
    for (int i = 0; i < 2; i++)
        #pragma unroll
        for (int j = 0; j < FN; j++)
            #pragma unroll
            for (int k = 0; k < 4; k++) acc[i][j][k] = 0.0f;

    #pragma unroll
    for (int s = 0; s < STAGES - 1; s++)
        if (s < nc) load_chunk(s, s);

    for (int c = 0; c < nc; c++) {
        if (c + 1 < nc) cp_wait<STAGES - 2>();
        else cp_wait<0>();
        __syncthreads();
        int nxt = c + STAGES - 1;
        if (nxt < nc) load_chunk(nxt, nxt % STAGES);

        int st = c % STAGES;
        uint32_t bufA = smb + (uint32_t)st * STAGE;
        uint32_t bufB = bufA + ABYTES;

        #pragma unroll
        for (int s = 0; s < 4; s++) {
            int kb = s * 32 + (lane >> 4) * 16;
            uint32_t aF[2][4], bF[FB][4];
            #pragma unroll
            for (int fm = 0; fm < 2; fm++) {
                uint32_t off = (uint32_t)(wm * 32 + fm * 16 + (lane & 15)) * 128 + kb;
                ldmatrix_x4(aF[fm], bufA + (off ^ ((off >> 3) & 0x70)));
            }
            #pragma unroll
            for (int fb = 0; fb < FB; fb++) {
                uint32_t off = (uint32_t)(wn * WNT + fb * 16 + (lane & 15)) * 128 + kb;
                ldmatrix_x4(bF[fb], bufB + (off ^ ((off >> 3) & 0x70)));
            }
            #pragma unroll
            for (int fm = 0; fm < 2; fm++)
                #pragma unroll
                for (int fn = 0; fn < FN; fn++) {
                    int fb = fn >> 1, odd = fn & 1;
                    mma16816(acc[fm][fn], aF[fm], bF[fb][odd], bF[fb][odd + 2]);
                }
        }
    }

    // epilogue
    #pragma unroll
    for (int fm = 0; fm < 2; fm++) {
        #pragma unroll
        for (int fn = 0; fn < FN; fn++) {
            int gr = row0 + wm * 32 + fm * 16 + (lane >> 2);
            int gc = col0 + wn * WNT + fn * 8 + 2 * (lane & 3);
            float v0 = acc[fm][fn][0], v1 = acc[fm][fn][1];
            float v2 = acc[fm][fn][2], v3 = acc[fm][fn][3];
            if (MODE >= 1) {
                float b0 = bias[gc], b1 = bias[gc + 1];
                v0 += b0; v1 += b1; v2 += b0; v3 += b1;
            }
            if (MODE == 2) {
                v0 += resid[(long)gr * N + gc];
                v1 += resid[(long)gr * N + gc + 1];
                v2 += resid[(long)(gr + 8) * N + gc];
                v3 += resid[(long)(gr + 8) * N + gc + 1];
            }
            if (MODE == 3) {
                v0 = fmaxf(v0, 0.0f); v1 = fmaxf(v1, 0.0f);
                v2 = fmaxf(v2, 0.0f); v3 = fmaxf(v3, 0.0f);
            }
            *(float2*)&C[(long)gr * N + gc] = make_float2(v0, v1);
            *(float2*)&C[(long)(gr + 8) * N + gc] = make_float2(v2, v3);
        }
    }
}

#define SMEM_BM128 (STAGES * (128 * 128 + 16384))
#define SMEM_BM64  (STAGES * (64 * 128 + 16384))

static void run_tc64(const __nv_bfloat16* A, const __nv_bfloat16* B, const float* bias,
                     const float* resid, float* C, int N, int K3, int mode) {
    dim3 grid(N / 128, BS_ / 64);
    if (mode == 0) mma_gemm_kernel<64, 0><<<grid, 256, SMEM_BM64>>>(A, B, bias, resid, C, N, K3);
    else           mma_gemm_kernel<64, 2><<<grid, 256, SMEM_BM64>>>(A, B, bias, resid, C, N, K3);
}
static void run_tc128(const __nv_bfloat16* A, const __nv_bfloat16* B, const float* bias,
                      const float* resid, float* C, int N, int K3, int mode) {
    dim3 grid(N / 128, BS_ / 128);
    if (mode == 1) mma_gemm_kernel<128, 1><<<grid, 256, SMEM_BM128>>>(A, B, bias, resid, C, N, K3);
    else           mma_gemm_kernel<128, 3><<<grid, 256, SMEM_BM128>>>(A, B, bias, resid, C, N, K3);
}

// ---------------- embedding ----------------
__global__ void embed_kernel(const int* __restrict__ tokens,
                             const float* __restrict__ tok_emb,
                             const float* __restrict__ pos_emb,
                             float* __restrict__ h) {
    int i = blockIdx.x * blockDim.x + threadIdx.x;
    if (i >= BS_ * D_) return;
    int d = i % D_;
    int bs = i / D_;
    int s = bs % S_;
    int tok = tokens[bs];
    h[i] = tok_emb[(size_t)tok * D_ + d] + pos_emb[(size_t)s * D_ + d];
}

// ---------------- layernorm ----------------
__global__ void layernorm_kernel(const float* __restrict__ x,
                                 const float* __restrict__ g,
                                 const float* __restrict__ b,
                                 float* __restrict__ y) {
    int row = blockIdx.x;
    const float* xr = x + (size_t)row * D_;
    float* yr = y + (size_t)row * D_;
    float vals[4];
    float s = 0.0f;
    #pragma unroll
    for (int j = 0; j < 4; j++) { vals[j] = xr[threadIdx.x + j * 256]; s += vals[j]; }
    float mean = blockReduceSum(s) * (1.0f / D_);
    float var = 0.0f;
    #pragma unroll
    for (int j = 0; j < 4; j++) { float d = vals[j] - mean; var += d * d; }
    var = blockReduceSum(var) * (1.0f / D_);
    float rstd = rsqrtf(var + 1e-5f);
    #pragma unroll
    for (int j = 0; j < 4; j++) {
        int i = threadIdx.x + j * 256;
        yr[i] = (vals[j] - mean) * rstd * g[i] + b[i];
    }
}

// ---------------- flash-tiled causal attention ----------------
// Block: 64 q-rows of one (b,h). 256 threads: thread = (r = tid>>2, c4 = tid&3).
// Keys interleaved: thread c4 owns keys kl = kk*4 + c4 (kk=0..15) of each 64-key tile.
// Output: thread owns dims c4*16 .. c4*16+15 of row r.
#define QT 64
#define ROWP 68  // padded row stride (floats), 16B-aligned
__global__ __launch_bounds__(256) void flash_attn_kernel(const float* __restrict__ QKV,
                                                         float* __restrict__ O) {
    extern __shared__ float fsm[];
    float* sQ = fsm;                 // [64][68]
    float* sK = fsm + 64 * ROWP;     // [64][68]
    float* sV = fsm + 2 * 64 * ROWP; // [64][68]
    float* sP = fsm + 3 * 64 * ROWP; // [64][68]

    int qt = blockIdx.x, h = blockIdx.y, b = blockIdx.z;
    int q0 = qt * QT;
    int tid = threadIdx.x;
    int r = tid >> 2, c4 = tid & 3;
    const float scale = 0.03125f;  // D^-0.5 (reference scales by embedding dim)

    // load Q tile: rows q0..q0+63, dims h*64..+63
    #pragma unroll
    for (int i = 0; i < 4; i++) {
        int lin = tid + i * 256;           // 0..1023 -> 16 float4 per row
        int rr = lin >> 4, cc = (lin & 15) * 4;
        float4 v = *(const float4*)&QKV[((size_t)(b * S_ + q0 + rr)) * K3D + h * DH_ + cc];
        *(float4*)&sQ[rr * ROWP + cc] = v;
    }

    float m_run = -1.0e30f, l_run = 0.0f;
    float acc[16];
    #pragma unroll
    for (int i = 0; i < 16; i++) acc[i] = 0.0f;

    for (int jt = 0; jt <= qt; jt++) {
        __syncthreads();
        int k0 = jt * QT;
        #pragma unroll
        for (int i = 0; i < 4; i++) {
            int lin = tid + i * 256;
            int rr = lin >> 4, cc = (lin & 15) * 4;
            size_t base = ((size_t)(b * S_ + k0 + rr)) * K3D + h * DH_ + cc;
            *(float4*)&sK[rr * ROWP + cc] = *(const float4*)&QKV[base + D_];
            *(float4*)&sV[rr * ROWP + cc] = *(const float4*)&QKV[base + 2 * D_];
        }
        __syncthreads();

        // scores for this thread's 16 keys
        float sc[16];
        float tmax = -1.0e30f;
        bool diag = (jt == qt);
        #pragma unroll
        for (int kk = 0; kk < 16; kk++) {
            int kl = kk * 4 + c4;
            float s = 0.0f;
            const float* qr = &sQ[r * ROWP];
            const float* kr = &sK[kl * ROWP];
            #pragma unroll
            for (int e = 0; e < DH_; e++) s = fmaf(qr[e], kr[e], s);
            s *= scale;
            if (diag && kl > r) s = -1.0e30f;
            sc[kk] = s;
            tmax = fmaxf(tmax, s);
        }
        // quad max (threads 4r..4r+3 are consecutive lanes)
        tmax = fmaxf(tmax, __shfl_xor_sync(0xffffffffu, tmax, 1));
        tmax = fmaxf(tmax, __shfl_xor_sync(0xffffffffu, tmax, 2));
        float m_new = fmaxf(m_run, tmax);
        float f = __expf(m_run - m_new);
        float sp = 0.0f;
        #pragma unroll
        for (int kk = 0; kk < 16; kk++) {
            float p = __expf(sc[kk] - m_new);
            sP[r * ROWP + kk * 4 + c4] = p;
            sp += p;
        }
        sp += __shfl_xor_sync(0xffffffffu, sp, 1);
        sp += __shfl_xor_sync(0xffffffffu, sp, 2);
        l_run = l_run * f + sp;
        m_run = m_new;
        #pragma unroll
        for (int i = 0; i < 16; i++) acc[i] *= f;
        __syncwarp();

        // PV: acc[d] += sum_kk p[r][kk] * V[kk][c4*16+d]
        const float* pr = &sP[r * ROWP];
        #pragma unroll 8
        for (int kk = 0; kk < 64; kk++) {
            float p = pr[kk];
            const float* vr = &sV[kk * ROWP + c4 * 16];
            #pragma unroll
            for (int d = 0; d < 16; d++) acc[d] = fmaf(p, vr[d], acc[d]);
        }
    }

    float inv = 1.0f / l_run;
    size_t obase = ((size_t)(b * S_ + q0 + r)) * D_ + h * DH_ + c4 * 16;
    #pragma unroll
    for (int d = 0; d < 16; d += 4) {
        float4 v = make_float4(acc[d] * inv, acc[d + 1] * inv, acc[d + 2] * inv, acc[d + 3] * inv);
        *(float4*)&O[obase + d] = v;
    }
}
#define ATTN_SMEM (4 * 64 * ROWP * 4)

// ---------------- loss ----------------
__global__ void zero_kernel(float* p) { *p = 0.0f; }

__global__ void loss_kernel(const float* __restrict__ logits,
                            const int* __restrict__ targets,
                            float* __restrict__ loss, float invN) {
    int row = blockIdx.x;
    const float* lr = logits + (size_t)row * V_;
    float lmax = -3.0e38f;
    for (int i = threadIdx.x; i < V_; i += blockDim.x) lmax = fmaxf(lmax, lr[i]);
    float m = blockReduceMax(lmax);
    float lsum = 0.0f;
    for (int i = threadIdx.x; i < V_; i += blockDim.x) lsum += __expf(lr[i] - m);
    float s = blockReduceSum(lsum);
    if (threadIdx.x == 0) {
        float lse = m + logf(s);
        float nll = lse - lr[targets[row]];
        atomicAdd(loss, nll * invN);
    }
}

// ---------------- launch ----------------
extern "C" void kernel_launch(void* const* d_in, const int* in_sizes, int n_in,
                              void* d_out, int out_size) {
    const int* tokens = (const int*)d_in[0];
    const int* targets = (const int*)d_in[1];
    const float* tok_emb = (const float*)d_in[2];
    const float* pos_emb = (const float*)d_in[3];
    const float* Wq = (const float*)d_in[4];
    const float* Wk = (const float*)d_in[5];
    const float* Wv = (const float*)d_in[6];
    const float* Wo = (const float*)d_in[7];
    const float* bo = (const float*)d_in[8];
    const float* ln1_g = (const float*)d_in[9];
    const float* ln1_b = (const float*)d_in[10];
    const float* ln2_g = (const float*)d_in[11];
    const float* ln2_b = (const float*)d_in[12];
    const float* W1 = (const float*)d_in[13];
    const float* b1 = (const float*)d_in[14];
    const float* W2 = (const float*)d_in[15];
    const float* b2 = (const float*)d_in[16];
    const float* lnf_g = (const float*)d_in[17];
    const float* lnf_b = (const float*)d_in[18];
    const float* Wout = (const float*)d_in[19];
    const float* bout = (const float*)d_in[20];
    float* out = (float*)d_out;

    cudaFuncSetAttribute((const void*)mma_gemm_kernel<64, 0>, cudaFuncAttributeMaxDynamicSharedMemorySize, SMEM_BM64);
    cudaFuncSetAttribute((const void*)mma_gemm_kernel<64, 2>, cudaFuncAttributeMaxDynamicSharedMemorySize, SMEM_BM64);
    cudaFuncSetAttribute((const void*)mma_gemm_kernel<128, 1>, cudaFuncAttributeMaxDynamicSharedMemorySize, SMEM_BM128);
    cudaFuncSetAttribute((const void*)mma_gemm_kernel<128, 3>, cudaFuncAttributeMaxDynamicSharedMemorySize, SMEM_BM128);
    cudaFuncSetAttribute((const void*)flash_attn_kernel, cudaFuncAttributeMaxDynamicSharedMemorySize, ATTN_SMEM);

    float *h, *xn, *qkv, *o, *ff;
    __nv_bfloat16 *abig, *bqkv, *bwo, *bw1, *bw2, *bwout;
    cudaGetSymbolAddress((void**)&h, g_h);
    cudaGetSymbolAddress((void**)&xn, g_xn);
    cudaGetSymbolAddress((void**)&qkv, g_qkv);
    cudaGetSymbolAddress((void**)&o, g_o);
    cudaGetSymbolAddress((void**)&ff, g_ff);
    cudaGetSymbolAddress((void**)&abig, g_abig);
    cudaGetSymbolAddress((void**)&bqkv, g_bqkv);
    cudaGetSymbolAddress((void**)&bwo, g_bwo);
    cudaGetSymbolAddress((void**)&bw1, g_bw1);
    cudaGetSymbolAddress((void**)&bw2, g_bw2);
    cudaGetSymbolAddress((void**)&bwout, g_bwout);

    // ---- weight prep: transpose to [N,K] and bf16x3 split ----
    dim3 tb(32, 8);
    transpose_split_kernel<<<dim3(2, 32, L_ * H_), tb>>>(Wq, bqkv, D_, DH_, (long)D_ * DH_, (long)K3D * K3D, H_, 0, K3D);
    transpose_split_kernel<<<dim3(2, 32, L_ * H_), tb>>>(Wk, bqkv, D_, DH_, (long)D_ * DH_, (long)K3D * K3D, H_, D_, K3D);
    transpose_split_kernel<<<dim3(2, 32, L_ * H_), tb>>>(Wv, bqkv, D_, DH_, (long)D_ * DH_, (long)K3D * K3D, H_, 2 * D_, K3D);
    transpose_split_kernel<<<dim3(32, 32, L_), tb>>>(Wo, bwo, D_, D_, (long)D_ * D_, (long)D_ * K3D, 1, 0, K3D);
    transpose_split_kernel<<<dim3(128, 32, L_), tb>>>(W1, bw1, D_, FF_, (long)D_ * FF_, (long)FF_ * K3D, 1, 0, K3D);
    transpose_split_kernel<<<dim3(32, 128, L_), tb>>>(W2, bw2, FF_, D_, (long)FF_ * D_, (long)D_ * K3F, 1, 0, K3F);
    transpose_split_kernel<<<dim3(1000, 32, 1), tb>>>(Wout, bwout, D_, V_, 0, 0, 1, 0, K3D);

    embed_kernel<<<(BS_ * D_ + 255) / 256, 256>>>(tokens, tok_emb, pos_emb, h);

    for (int l = 0; l < L_; l++) {
        layernorm_kernel<<<BS_, 256>>>(h, ln1_g + (size_t)l * D_, ln1_b + (size_t)l * D_, xn);
        act_split_kernel<<<BS_ * D_ / 256, 256>>>(xn, abig, D_);
        run_tc64(abig, bqkv + (size_t)l * K3D * K3D, nullptr, nullptr, qkv, K3D, K3D, 0);
        dim3 ag(S_ / QT, H_, B_);
        flash_attn_kernel<<<ag, 256, ATTN_SMEM>>>(qkv, o);
        act_split_kernel<<<BS_ * D_ / 256, 256>>>(o, abig, D_);
        run_tc64(abig, bwo + (size_t)l * D_ * K3D, bo + (size_t)l * D_, h, h, D_, K3D, 2);
        layernorm_kernel<<<BS_, 256>>>(h, ln2_g + (size_t)l * D_, ln2_b + (size_t)l * D_, xn);
        act_split_kernel<<<BS_ * D_ / 256, 256>>>(xn, abig, D_);
        run_tc128(abig, bw1 + (size_t)l * FF_ * K3D, b1 + (size_t)l * FF_, nullptr, ff, FF_, K3D, 3);
        act_split_kernel<<<BS_ * FF_ / 256, 256>>>(ff, abig, FF_);
        run_tc64(abig, bw2 + (size_t)l * D_ * K3F, b2 + (size_t)l * D_, h, h, D_, K3F, 2);
    }

    layernorm_kernel<<<BS_, 256>>>(h, lnf_g, lnf_b, xn);
    act_split_kernel<<<BS_ * D_ / 256, 256>>>(xn, abig, D_);
    run_tc128(abig, bwout, bout, nullptr, out, V_, K3D, 1);

    long long BSV = (long long)BS_ * V_;
    if ((long long)out_size > BSV) {
        zero_kernel<<<1, 1>>>(out + BSV);
        loss_kernel<<<BS_, 256>>>(out, targets, out + BSV, 1.0f / BS_);
    }
}